// round 15
// baseline (speedup 1.0000x reference)
#include <cuda_runtime.h>
#include <cstdint>
#include <math.h>

// DotAttention: context[b,f] = sum_t softmax_t(<hd[b],he[b,t]>) * he[b,t,f]
// b=64, t=2048, f=1024, fp32.
//
// Single-pass online softmax, register-direct coalesced LDG.128 (best
// measured mainloop). This round: 3 CTAs/SM (reg cap 85 via launch_bounds)
// to raise warps/SM 16->24 and keep more DRAM bytes outstanding.
// Fused split-merge via atomic ticket.

#define BATCH   64
#define TOK     2048
#define FDIM    1024
#define F4      (FDIM / 4)      // 256 float4 per row
#define SPLITS  8
#define TCHUNK  (TOK / SPLITS)  // 256 tokens per CTA
#define NWARP   8               // 256 threads

// Scratch (allocation-free __device__ globals)
__device__ float4 g_part_ctx[BATCH * SPLITS * F4];  // 2 MB
__device__ float  g_part_m[BATCH * SPLITS];
__device__ float  g_part_l[BATCH * SPLITS];
__device__ int    g_cnt[BATCH];                     // zero-init; self-resets

__global__ __launch_bounds__(256, 3)
void dotattn_fused(const float* __restrict__ hd, const float* __restrict__ he,
                   float* __restrict__ out)
{
    const int b    = blockIdx.y;
    const int s    = blockIdx.x;
    const int tid  = threadIdx.x;
    const int lane = tid & 31;
    const int warp = tid >> 5;

    __shared__ float4 s_q[F4];              // 4 KB
    __shared__ float4 s_acc[NWARP][F4];     // 32 KB
    __shared__ float  s_m[NWARP], s_l[NWARP];
    __shared__ int    s_last;

    // Stage q = hd[b,:] into smem
    {
        const float4* hd4 = (const float4*)(hd + (size_t)b * FDIM);
        if (tid < F4) s_q[tid] = hd4[tid];
    }
    __syncthreads();

    // Per-lane state. Lane covers f4 indices j*32+lane -> each j is a 512B
    // contiguous warp load (fully coalesced LDG.128).
    float  m = -INFINITY;
    float  l = 0.0f;
    float4 acc[8];
#pragma unroll
    for (int j = 0; j < 8; j++) acc[j] = make_float4(0.f, 0.f, 0.f, 0.f);

    const int t0 = s * TCHUNK;
    for (int t = t0 + warp; t < t0 + TCHUNK; t += NWARP) {
        const float4* he4 = (const float4*)(he + ((size_t)b * TOK + t) * FDIM);

        float4 v[8];
#pragma unroll
        for (int j = 0; j < 8; j++) v[j] = he4[j * 32 + lane];

        float sc = 0.0f;
#pragma unroll
        for (int j = 0; j < 8; j++) {
            float4 q = s_q[j * 32 + lane];
            sc += v[j].x * q.x + v[j].y * q.y + v[j].z * q.z + v[j].w * q.w;
        }
#pragma unroll
        for (int o = 16; o > 0; o >>= 1)
            sc += __shfl_xor_sync(0xffffffffu, sc, o);

        const float nm   = fmaxf(m, sc);
        const float corr = __expf(m - nm);   // exp(-inf)=0 on first iter
        const float w    = __expf(sc - nm);
        l = l * corr + w;
        m = nm;
#pragma unroll
        for (int j = 0; j < 8; j++) {
            acc[j].x = acc[j].x * corr + w * v[j].x;
            acc[j].y = acc[j].y * corr + w * v[j].y;
            acc[j].z = acc[j].z * corr + w * v[j].z;
            acc[j].w = acc[j].w * corr + w * v[j].w;
        }
    }

    // ---- merge the 8 warps of this CTA ----
#pragma unroll
    for (int j = 0; j < 8; j++) s_acc[warp][j * 32 + lane] = acc[j];
    if (lane == 0) { s_m[warp] = m; s_l[warp] = l; }
    __syncthreads();

    float M = s_m[0];
#pragma unroll
    for (int w2 = 1; w2 < NWARP; w2++) M = fmaxf(M, s_m[w2]);
    float L = 0.0f;
    float4 c = make_float4(0.f, 0.f, 0.f, 0.f);
#pragma unroll
    for (int w2 = 0; w2 < NWARP; w2++) {
        const float e = __expf(s_m[w2] - M);
        L += s_l[w2] * e;
        float4 a = s_acc[w2][tid];
        c.x += a.x * e;
        c.y += a.y * e;
        c.z += a.z * e;
        c.w += a.w * e;
    }
    g_part_ctx[((size_t)b * SPLITS + s) * F4 + tid] = c;
    if (tid == 0) {
        g_part_m[b * SPLITS + s] = M;
        g_part_l[b * SPLITS + s] = L;
    }

    // ---- fused cross-split finalize: last CTA of batch b reduces ----
    __threadfence();   // release partials
    if (tid == 0) {
        const int prev = atomicAdd(&g_cnt[b], 1);
        s_last = (prev == SPLITS - 1);
    }
    __syncthreads();
    if (!s_last) return;

    __threadfence();   // acquire

    const int base = b * SPLITS;
    float gm = -INFINITY;
#pragma unroll
    for (int sp = 0; sp < SPLITS; sp++) gm = fmaxf(gm, g_part_m[base + sp]);

    float gl = 0.0f;
    float4 o = make_float4(0.f, 0.f, 0.f, 0.f);
#pragma unroll
    for (int sp = 0; sp < SPLITS; sp++) {
        const float e = __expf(g_part_m[base + sp] - gm);
        gl += g_part_l[base + sp] * e;
        float4 a = g_part_ctx[(size_t)(base + sp) * F4 + tid];
        o.x += a.x * e;
        o.y += a.y * e;
        o.z += a.z * e;
        o.w += a.w * e;
    }
    const float inv = 1.0f / gl;
    o.x *= inv; o.y *= inv; o.z *= inv; o.w *= inv;
    ((float4*)out)[(size_t)b * F4 + tid] = o;

    __syncthreads();
    if (tid == 0) g_cnt[b] = 0;   // reset for next graph replay
}

extern "C" void kernel_launch(void* const* d_in, const int* in_sizes, int n_in,
                              void* d_out, int out_size)
{
    const float* hd = (const float*)d_in[0];  // (64, 1024)
    const float* he = (const float*)d_in[1];  // (64, 2048, 1024)
    float* out = (float*)d_out;               // (64, 1024)

    dim3 grid(SPLITS, BATCH);
    dotattn_fused<<<grid, 256>>>(hd, he, out);
}

// round 16
// speedup vs baseline: 1.7678x; 1.7678x over previous
#include <cuda_runtime.h>
#include <cstdint>
#include <math.h>

// DotAttention: context[b,f] = sum_t softmax_t(<hd[b],he[b,t]>) * he[b,t,f]
// b=64, t=2048, f=1024, fp32.
//
// Single-pass online softmax, register-direct coalesced LDG.128 (best
// measured mainloop, R6 body) + L2 prefetch: one prefetch.global.L2 per
// token row (lane covers a distinct 128B line), issued 2 warp-iterations
// ahead. Demand loads then hit L2 (~250cyc) instead of DRAM (~600cyc),
// cutting the latency the 1KB/warp in-flight window must cover.
// Fused split-merge via atomic ticket.

#define BATCH   64
#define TOK     2048
#define FDIM    1024
#define F4      (FDIM / 4)      // 256 float4 per row
#define SPLITS  8
#define TCHUNK  (TOK / SPLITS)  // 256 tokens per CTA
#define NWARP   8               // 256 threads

// Scratch (allocation-free __device__ globals)
__device__ float4 g_part_ctx[BATCH * SPLITS * F4];  // 2 MB
__device__ float  g_part_m[BATCH * SPLITS];
__device__ float  g_part_l[BATCH * SPLITS];
__device__ int    g_cnt[BATCH];                     // zero-init; self-resets

__global__ __launch_bounds__(256, 2)
void dotattn_fused(const float* __restrict__ hd, const float* __restrict__ he,
                   float* __restrict__ out)
{
    const int b    = blockIdx.y;
    const int s    = blockIdx.x;
    const int tid  = threadIdx.x;
    const int lane = tid & 31;
    const int warp = tid >> 5;

    __shared__ float4 s_q[F4];              // 4 KB
    __shared__ float4 s_acc[NWARP][F4];     // 32 KB
    __shared__ float  s_m[NWARP], s_l[NWARP];
    __shared__ int    s_last;

    // Stage q = hd[b,:] into smem
    {
        const float4* hd4 = (const float4*)(hd + (size_t)b * FDIM);
        if (tid < F4) s_q[tid] = hd4[tid];
    }
    __syncthreads();

    const float* he_b = he + (size_t)b * TOK * FDIM;

    // Per-lane state. Lane covers f4 indices j*32+lane -> each j is a 512B
    // contiguous warp load (fully coalesced LDG.128).
    float  m = -INFINITY;
    float  l = 0.0f;
    float4 acc[8];
#pragma unroll
    for (int j = 0; j < 8; j++) acc[j] = make_float4(0.f, 0.f, 0.f, 0.f);

    const int t0 = s * TCHUNK;

    // prime the L2 prefetch pipeline for this warp's first two tokens
#pragma unroll
    for (int d = 0; d < 2; d++) {
        const int t_pf = t0 + warp + d * NWARP;
        const char* p = (const char*)(he_b + (size_t)t_pf * FDIM) + lane * 128;
        asm volatile("prefetch.global.L2 [%0];" :: "l"(p));
    }

    for (int t = t0 + warp; t < t0 + TCHUNK; t += NWARP) {
        // prefetch 2 iterations ahead (whole 4KB row: 32 lanes x 128B)
        {
            const int t_pf = t + 2 * NWARP;
            if (t_pf < TOK) {
                const char* p = (const char*)(he_b + (size_t)t_pf * FDIM) + lane * 128;
                asm volatile("prefetch.global.L2 [%0];" :: "l"(p));
            }
        }

        const float4* he4 = (const float4*)(he_b + (size_t)t * FDIM);

        float4 v[8];
#pragma unroll
        for (int j = 0; j < 8; j++) v[j] = he4[j * 32 + lane];

        float sc = 0.0f;
#pragma unroll
        for (int j = 0; j < 8; j++) {
            float4 q = s_q[j * 32 + lane];
            sc += v[j].x * q.x + v[j].y * q.y + v[j].z * q.z + v[j].w * q.w;
        }
#pragma unroll
        for (int o = 16; o > 0; o >>= 1)
            sc += __shfl_xor_sync(0xffffffffu, sc, o);

        const float nm   = fmaxf(m, sc);
        const float corr = __expf(m - nm);   // exp(-inf)=0 on first iter
        const float w    = __expf(sc - nm);
        l = l * corr + w;
        m = nm;
#pragma unroll
        for (int j = 0; j < 8; j++) {
            acc[j].x = acc[j].x * corr + w * v[j].x;
            acc[j].y = acc[j].y * corr + w * v[j].y;
            acc[j].z = acc[j].z * corr + w * v[j].z;
            acc[j].w = acc[j].w * corr + w * v[j].w;
        }
    }

    // ---- merge the 8 warps of this CTA ----
#pragma unroll
    for (int j = 0; j < 8; j++) s_acc[warp][j * 32 + lane] = acc[j];
    if (lane == 0) { s_m[warp] = m; s_l[warp] = l; }
    __syncthreads();

    float M = s_m[0];
#pragma unroll
    for (int w2 = 1; w2 < NWARP; w2++) M = fmaxf(M, s_m[w2]);
    float L = 0.0f;
    float4 c = make_float4(0.f, 0.f, 0.f, 0.f);
#pragma unroll
    for (int w2 = 0; w2 < NWARP; w2++) {
        const float e = __expf(s_m[w2] - M);
        L += s_l[w2] * e;
        float4 a = s_acc[w2][tid];
        c.x += a.x * e;
        c.y += a.y * e;
        c.z += a.z * e;
        c.w += a.w * e;
    }
    g_part_ctx[((size_t)b * SPLITS + s) * F4 + tid] = c;
    if (tid == 0) {
        g_part_m[b * SPLITS + s] = M;
        g_part_l[b * SPLITS + s] = L;
    }

    // ---- fused cross-split finalize: last CTA of batch b reduces ----
    __threadfence();   // release partials
    if (tid == 0) {
        const int prev = atomicAdd(&g_cnt[b], 1);
        s_last = (prev == SPLITS - 1);
    }
    __syncthreads();
    if (!s_last) return;

    __threadfence();   // acquire

    const int base = b * SPLITS;
    float gm = -INFINITY;
#pragma unroll
    for (int sp = 0; sp < SPLITS; sp++) gm = fmaxf(gm, g_part_m[base + sp]);

    float gl = 0.0f;
    float4 o = make_float4(0.f, 0.f, 0.f, 0.f);
#pragma unroll
    for (int sp = 0; sp < SPLITS; sp++) {
        const float e = __expf(g_part_m[base + sp] - gm);
        gl += g_part_l[base + sp] * e;
        float4 a = g_part_ctx[(size_t)(base + sp) * F4 + tid];
        o.x += a.x * e;
        o.y += a.y * e;
        o.z += a.z * e;
        o.w += a.w * e;
    }
    const float inv = 1.0f / gl;
    o.x *= inv; o.y *= inv; o.z *= inv; o.w *= inv;
    ((float4*)out)[(size_t)b * F4 + tid] = o;

    __syncthreads();
    if (tid == 0) g_cnt[b] = 0;   // reset for next graph replay
}

extern "C" void kernel_launch(void* const* d_in, const int* in_sizes, int n_in,
                              void* d_out, int out_size)
{
    const float* hd = (const float*)d_in[0];  // (64, 1024)
    const float* he = (const float*)d_in[1];  // (64, 2048, 1024)
    float* out = (float*)d_out;               // (64, 1024)

    dim3 grid(SPLITS, BATCH);
    dotattn_fused<<<grid, 256>>>(hd, he, out);
}